// round 9
// baseline (speedup 1.0000x reference)
#include <cuda_runtime.h>
#include <cuda_fp16.h>
#include <cstdint>

#define HW 4096
#define DDIM 64
#define NSLICE 256          // total K slices of 16
#define QSLICE 64           // slices per K-quarter (per warp)
#define TM 32               // rows per CTA

// B fragments, lane-major: g_fp[gs][q][lane][4 x b32]; uint4 index = gs*128 + q*32 + lane
// K-permutation (matches float4 A loads): real k = (l&3)*4 + pair*2
__device__ uint32_t g_fp[NSLICE * 4 * 32 * 4];

// ---------------------------------------------------------------------------
// Kernel 1: build packed B fragments of f[m,d] = cos(8pi*(w0*gx + w1*gy + b))
// ---------------------------------------------------------------------------
__global__ void pos_enc_kernel(const float* __restrict__ w,
                               const float* __restrict__ bias) {
    int idx = blockIdx.x * blockDim.x + threadIdx.x;
    if (idx >= NSLICE * 512) return;
    int c    = idx & 3;
    int l    = (idx >> 2) & 31;
    int q    = (idx >> 7) & 3;
    int gs   = idx >> 9;
    int j    = q * 2 + (c >> 1);
    int pair = c & 1;
    int d    = j * 8 + (l >> 2);
    int k    = (l & 3) * 4 + pair * 2;
    int m0   = gs * 16 + k;
    float w0 = w[2 * d], w1 = w[2 * d + 1], bd = bias[d];
    float v[2];
#pragma unroll
    for (int t = 0; t < 2; t++) {
        int m = m0 + t;
        int x = m & 63, y = m >> 6;
        float gx = (float)(2 * x - 63) * (1.0f / 64.0f);
        float gy = (float)(2 * y - 63) * (1.0f / 64.0f);
        v[t] = cosf(25.132741228718345f * fmaf(w0, gx, fmaf(w1, gy, bd)));
    }
    __half2 h = __floats2half2_rn(v[0], v[1]);
    g_fp[idx] = *reinterpret_cast<uint32_t*>(&h);
}

// ---------------------------------------------------------------------------
#define MMA(dst, a0, a1, a2, a3, b0, b1)                                        \
    asm volatile("mma.sync.aligned.m16n8k16.row.col.f32.f16.f16.f32 "           \
                 "{%0,%1,%2,%3},{%4,%5,%6,%7},{%8,%9},{%0,%1,%2,%3};"           \
                 : "+f"(dst[0]), "+f"(dst[1]), "+f"(dst[2]), "+f"(dst[3])       \
                 : "r"(a0), "r"(a1), "r"(a2), "r"(a3), "r"(b0), "r"(b1))

// issue A copy for slice s into warp-private ring slot j
#define CPA(j, s)                                                               \
    do { const float* _g = pA + (size_t)(s) * 16;                               \
        uint32_t _d = ringw + (j) * 1024 + l * 16;                              \
        asm volatile("cp.async.cg.shared.global [%0], [%1], 16;"                \
                     :: "r"(_d), "l"(_g) : "memory");                           \
        asm volatile("cp.async.cg.shared.global [%0], [%1], 16;"                \
                     :: "r"(_d + 512), "l"(_g + 8 * HW) : "memory");            \
    } while (0)

#define STAGE(j, sidx)                                                          \
    do {                                                                        \
        if ((sidx) + 3 < QSLICE) { CPA(((sidx) + 3) & 3, (sidx) + 3); }         \
        asm volatile("cp.async.commit_group;" ::: "memory");                    \
        asm volatile("cp.async.wait_group 3;" ::: "memory");                    \
        const uint4* _bp = pB + (size_t)(sidx) * 128;                           \
        uint4 B0 = __ldg(_bp);      uint4 B1 = __ldg(_bp + 32);                 \
        uint4 B2 = __ldg(_bp + 64); uint4 B3 = __ldg(_bp + 96);                 \
        float4 A0 = *(const float4*)(smRing + (j) * 1024 + l * 16);             \
        float4 A1 = *(const float4*)(smRing + (j) * 1024 + 512 + l * 16);       \
        float e0 = __expf(A0.x), e1 = __expf(A0.y);                             \
        float e2 = __expf(A0.z), e3 = __expf(A0.w);                             \
        float e4 = __expf(A1.x), e5 = __expf(A1.y);                             \
        float e6 = __expf(A1.z), e7 = __expf(A1.w);                             \
        z0 += (e0 + e1) + (e2 + e3);                                            \
        z1 += (e4 + e5) + (e6 + e7);                                            \
        __half2 h0 = __floats2half2_rn(e0, e1);                                 \
        __half2 h1 = __floats2half2_rn(e2, e3);                                 \
        __half2 h2 = __floats2half2_rn(e4, e5);                                 \
        __half2 h3 = __floats2half2_rn(e6, e7);                                 \
        uint32_t ra0 = *reinterpret_cast<uint32_t*>(&h0);                       \
        uint32_t ra2 = *reinterpret_cast<uint32_t*>(&h1);                       \
        uint32_t ra1 = *reinterpret_cast<uint32_t*>(&h2);                       \
        uint32_t ra3 = *reinterpret_cast<uint32_t*>(&h3);                       \
        MMA(acc[0], ra0, ra1, ra2, ra3, B0.x, B0.y);                            \
        MMA(acc[1], ra0, ra1, ra2, ra3, B0.z, B0.w);                            \
        MMA(acc[2], ra0, ra1, ra2, ra3, B1.x, B1.y);                            \
        MMA(acc[3], ra0, ra1, ra2, ra3, B1.z, B1.w);                            \
        MMA(acc[4], ra0, ra1, ra2, ra3, B2.x, B2.y);                            \
        MMA(acc[5], ra0, ra1, ra2, ra3, B2.z, B2.w);                            \
        MMA(acc[6], ra0, ra1, ra2, ra3, B3.x, B3.y);                            \
        MMA(acc[7], ra0, ra1, ra2, ra3, B3.z, B3.w);                            \
    } while (0)

struct SmemT {
    union {
        float4 ring[8 * 4 * 64];       // 8 warps x 4 slots x 1KB = 32 KB
        struct {
            float Cs[TM][66];          // merged C, 8448 B
            float Zs[TM];
            float Zr[TM];
        } e;
    } u;
};

// ---------------------------------------------------------------------------
// Kernel 2: 256-thr CTA = 2 row-groups(16) x 4 K-quarters. Warp: 16r x 64N x K=1024.
// Warp-private cp.async A ring (depth 4, L1-bypass). B on-demand (L1-hot).
// Grid 512 CTAs -> 3 CTAs/SM (launch_bounds(256,3)), 24 warps/SM.
// ---------------------------------------------------------------------------
__global__ __launch_bounds__(256, 3)
void gp_kernel(const float* __restrict__ sim, float* __restrict__ out) {
    __shared__ SmemT sm;

    const int tid = threadIdx.x;
    const int l   = tid & 31;
    const int w   = tid >> 5;
    const int wm  = w & 1;        // row group (16 rows)
    const int kq  = w >> 1;       // K quarter
    const int bb  = blockIdx.y;
    const int row0 = blockIdx.x * TM;

    const float* pA = sim + ((size_t)bb * HW + row0 + wm * 16 + (l >> 2)) * (size_t)HW
                          + kq * (QSLICE * 16) + (l & 3) * 4;
    const uint4* pB = ((const uint4*)g_fp) + (size_t)kq * QSLICE * 128 + l;

    uint32_t ring_base;
    asm("{ .reg .u64 t; cvta.to.shared.u64 t, %1; cvt.u32.u64 %0, t; }"
        : "=r"(ring_base) : "l"((void*)&sm.u.ring[0]));
    const uint32_t ringw = ring_base + w * 4096;
    const char* smRing = (const char*)&sm.u.ring[0] + w * 4096;

    float acc[8][4];
#pragma unroll
    for (int i = 0; i < 8; i++)
#pragma unroll
        for (int k = 0; k < 4; k++) acc[i][k] = 0.0f;

    float z0 = 0.0f, z1 = 0.0f;

    CPA(0, 0);
    asm volatile("cp.async.commit_group;" ::: "memory");
    CPA(1, 1);
    asm volatile("cp.async.commit_group;" ::: "memory");
    CPA(2, 2);
    asm volatile("cp.async.commit_group;" ::: "memory");

#pragma unroll 1
    for (int s = 0; s < QSLICE; s += 4) {
        STAGE(0, s);
        STAGE(1, s + 1);
        STAGE(2, s + 2);
        STAGE(3, s + 3);
    }

    // ---- epilogue: quad-reduce Z, merge 4 K-quarters, divide, store ----
    z0 += __shfl_xor_sync(0xFFFFFFFFu, z0, 1);
    z0 += __shfl_xor_sync(0xFFFFFFFFu, z0, 2);
    z1 += __shfl_xor_sync(0xFFFFFFFFu, z1, 1);
    z1 += __shfl_xor_sync(0xFFFFFFFFu, z1, 2);

    __syncthreads();   // all ring reads done before union reuse
    const int lr = wm * 16 + (l >> 2);
    if (kq == 0) {
#pragma unroll
        for (int j = 0; j < 8; j++) {
            const int c0 = j * 8 + (l & 3) * 2;
            *(float2*)&sm.u.e.Cs[lr][c0]     = make_float2(acc[j][0], acc[j][1]);
            *(float2*)&sm.u.e.Cs[lr + 8][c0] = make_float2(acc[j][2], acc[j][3]);
        }
        if ((l & 3) == 0) { sm.u.e.Zs[lr] = z0; sm.u.e.Zs[lr + 8] = z1; }
    }
#pragma unroll
    for (int q = 1; q < 4; q++) {
        __syncthreads();
        if (kq == q) {
#pragma unroll
            for (int j = 0; j < 8; j++) {
                const int c0 = j * 8 + (l & 3) * 2;
                sm.u.e.Cs[lr][c0]         += acc[j][0];
                sm.u.e.Cs[lr][c0 + 1]     += acc[j][1];
                sm.u.e.Cs[lr + 8][c0]     += acc[j][2];
                sm.u.e.Cs[lr + 8][c0 + 1] += acc[j][3];
            }
            if ((l & 3) == 0) { sm.u.e.Zs[lr] += z0; sm.u.e.Zs[lr + 8] += z1; }
        }
    }
    __syncthreads();
    if (tid < TM) sm.u.e.Zr[tid] = 1.0f / sm.u.e.Zs[tid];
    __syncthreads();

    {
        const int d = tid >> 2, seg = tid & 3;
        float* go = out + ((size_t)(bb * DDIM + d)) * HW + row0 + seg * 8;
#pragma unroll
        for (int i = 0; i < 2; i++) {
            float4 o;
#pragma unroll
            for (int k = 0; k < 4; k++) {
                const int n = seg * 8 + i * 4 + k;
                (&o.x)[k] = sm.u.e.Cs[n][d] * sm.u.e.Zr[n];
            }
            *(float4*)(go + i * 4) = o;
        }
    }
}

// ---------------------------------------------------------------------------
extern "C" void kernel_launch(void* const* d_in, const int* in_sizes, int n_in,
                              void* d_out, int out_size) {
    const float* sim  = (const float*)d_in[0];  // [4, 4096, 4096] fp32
    const float* w    = (const float*)d_in[1];  // [64, 2] fp32
    const float* bias = (const float*)d_in[2];  // [64] fp32
    float* out = (float*)d_out;                 // [4, 64, 64, 64] fp32

    pos_enc_kernel<<<(NSLICE * 512 + 255) / 256, 256>>>(w, bias);

    dim3 grid(HW / TM, 4);
    gp_kernel<<<grid, 256>>>(sim, out);
}

// round 10
// speedup vs baseline: 1.8760x; 1.8760x over previous
#include <cuda_runtime.h>
#include <cuda_fp16.h>
#include <cstdint>

#define HW 4096
#define DDIM 64
#define NSLICE 256          // total K slices of 16
#define HSLICE 128          // slices per K-half
#define NBLK 64             // 32-wide K blocks per K-half
#define CS_STRIDE 66

// B fragments, lane-major: g_fp[slice][q][lane][4 x b32]; uint4 index = s*128 + q*32 + l
// ISA->real K map (per 32-block, full-line A loads): real = 8*(l&3) + 4*(s&1) + 2*pair + t
__device__ uint32_t g_fp[NSLICE * 4 * 32 * 4];

// ---------------------------------------------------------------------------
// Kernel 1: build packed B fragments of f[m,d] = cos(8pi*(w0*gx + w1*gy + b))
// ---------------------------------------------------------------------------
__global__ void pos_enc_kernel(const float* __restrict__ w,
                               const float* __restrict__ bias) {
    int idx = blockIdx.x * blockDim.x + threadIdx.x;
    if (idx >= NSLICE * 512) return;
    int c    = idx & 3;        // uint4 component
    int l    = (idx >> 2) & 31;
    int q    = (idx >> 7) & 3;
    int gs   = idx >> 9;       // slice
    int j    = q * 2 + (c >> 1);   // n-frag (cols j*8..j*8+7)
    int pair = c & 1;              // b0 (ISA k-lo) / b1 (ISA k-hi)
    int d    = j * 8 + (l >> 2);
    int m0   = (gs >> 1) * 32 + ((l & 3) << 3) + ((gs & 1) << 2) + (pair << 1);
    float w0 = w[2 * d], w1 = w[2 * d + 1], bd = bias[d];
    float v[2];
#pragma unroll
    for (int t = 0; t < 2; t++) {
        int m = m0 + t;
        int x = m & 63, y = m >> 6;
        float gx = (float)(2 * x - 63) * (1.0f / 64.0f);
        float gy = (float)(2 * y - 63) * (1.0f / 64.0f);
        v[t] = cosf(25.132741228718345f * fmaf(w0, gx, fmaf(w1, gy, bd)));
    }
    __half2 h = __floats2half2_rn(v[0], v[1]);
    g_fp[idx] = *reinterpret_cast<uint32_t*>(&h);
}

// ---------------------------------------------------------------------------
static __device__ __forceinline__ uint32_t e2p(float a, float b) {
    __half2 h = __floats2half2_rn(__expf(a), __expf(b));
    return *reinterpret_cast<uint32_t*>(&h);
}

#define MMA(dst, a0, a1, a2, a3, b0, b1)                                        \
    asm volatile("mma.sync.aligned.m16n8k16.row.col.f32.f16.f16.f32 "           \
                 "{%0,%1,%2,%3},{%4,%5,%6,%7},{%8,%9},{%0,%1,%2,%3};"           \
                 : "+f"(dst[0]), "+f"(dst[1]), "+f"(dst[2]), "+f"(dst[3])       \
                 : "r"(a0), "r"(a1), "r"(a2), "r"(a3), "r"(b0), "r"(b1))

// Load one 32-wide K block: thread reads 32B consecutive of rows l/4, l/4+8.
// Quad covers the full 128B line -> 4 lines per LDG; pair miss-merges.
#define LA(st, b)                                                               \
    do { const float* _p = pA + (size_t)(b) * 32;                               \
        R[st][0] = __ldcs((const float4*)_p);                                   \
        R[st][1] = __ldcs((const float4*)(_p + 4));                             \
        R[st][2] = __ldcs((const float4*)(_p + 8 * HW));                        \
        R[st][3] = __ldcs((const float4*)(_p + 8 * HW + 4)); } while (0)

// One 16-slice: on-demand B, 4 packs, 9 MMAs. rl/rh = float4 pair (row lo/hi)
#define HALF_STAGE(sidx, rl, rh, do_la, st, blk)                                \
    do {                                                                        \
        const uint4* _bp = pB + (size_t)(sidx) * 128;                           \
        uint4 B0 = __ldg(_bp);      uint4 B1 = __ldg(_bp + 32);                 \
        uint4 B2 = __ldg(_bp + 64); uint4 B3 = __ldg(_bp + 96);                 \
        uint32_t ra0 = e2p(rl.x, rl.y);                                         \
        uint32_t ra2 = e2p(rl.z, rl.w);                                         \
        uint32_t ra1 = e2p(rh.x, rh.y);                                         \
        uint32_t ra3 = e2p(rh.z, rh.w);                                         \
        if (do_la && (blk) + 2 < NBLK) LA(st, (blk) + 2);                       \
        MMA(acc[0], ra0, ra1, ra2, ra3, B0.x, B0.y);                            \
        MMA(acc[1], ra0, ra1, ra2, ra3, B0.z, B0.w);                            \
        MMA(acc[2], ra0, ra1, ra2, ra3, B1.x, B1.y);                            \
        MMA(acc[3], ra0, ra1, ra2, ra3, B1.z, B1.w);                            \
        MMA(acc[4], ra0, ra1, ra2, ra3, B2.x, B2.y);                            \
        MMA(acc[5], ra0, ra1, ra2, ra3, B2.z, B2.w);                            \
        MMA(acc[6], ra0, ra1, ra2, ra3, B3.x, B3.y);                            \
        MMA(acc[7], ra0, ra1, ra2, ra3, B3.z, B3.w);                            \
        MMA(acc[8], ra0, ra1, ra2, ra3, bz, bz);                                \
    } while (0)

// Block stage: slice 2b uses R[st][0](row lo)/R[st][2](row hi); slice 2b+1 uses R[st][1]/R[st][3]
#define STAGE(st, blk)                                                          \
    do {                                                                        \
        HALF_STAGE(2 * (blk),     R[st][0], R[st][2], 0, st, blk);              \
        HALF_STAGE(2 * (blk) + 1, R[st][1], R[st][3], 1, st, blk);              \
    } while (0)

// ---------------------------------------------------------------------------
// Kernel 2: 8 warps = 4 row-groups x 2 K-halves. Warp: 16 rows x 64 N x K=2048.
// Full-line A loads (8 wf/slice), on-demand B, Z via 9th MMA.
// No smem/barriers in mainloop.
// ---------------------------------------------------------------------------
__global__ __launch_bounds__(256, 2)
void gp_kernel(const float* __restrict__ sim, float* __restrict__ out) {
    __shared__ float Cs[64][CS_STRIDE];
    __shared__ float Zs[64];
    __shared__ float Zr[64];

    const int tid = threadIdx.x;
    const int l   = tid & 31;
    const int w   = tid >> 5;
    const int wm  = w & 3;       // row group
    const int kh  = w >> 2;      // K half
    const int bb  = blockIdx.y;
    const int row0 = blockIdx.x * 64;

    // thread reads 32B consecutive at (l&3)*32B within each 128B K-block of row l/4
    const float* pA = sim + ((size_t)bb * HW + row0 + wm * 16 + (l >> 2)) * (size_t)HW
                          + kh * (HSLICE * 16) + (l & 3) * 8;
    const uint4* pB = ((const uint4*)g_fp) + (size_t)kh * HSLICE * 128 + l;

    float acc[9][4];
#pragma unroll
    for (int i = 0; i < 9; i++)
#pragma unroll
        for (int k = 0; k < 4; k++) acc[i][k] = 0.0f;

    const uint32_t bz = (l < 4) ? 0x3C003C00u : 0u;  // ones in B col n=0

    float4 R[2][4];
    LA(0, 0); LA(1, 1);

#pragma unroll 1
    for (int b = 0; b < NBLK; b += 2) {
        STAGE(0, b);
        STAGE(1, b + 1);
    }

    // ---- epilogue: merge K-halves via smem, divide by Z, coalesced store ----
    const int lr = wm * 16 + (l >> 2);
    if (kh == 0) {
#pragma unroll
        for (int j = 0; j < 8; j++) {
            const int c0 = j * 8 + (l & 3) * 2;
            *(float2*)&Cs[lr][c0]     = make_float2(acc[j][0], acc[j][1]);
            *(float2*)&Cs[lr + 8][c0] = make_float2(acc[j][2], acc[j][3]);
        }
        if ((l & 3) == 0) { Zs[lr] = acc[8][0]; Zs[lr + 8] = acc[8][2]; }
    }
    __syncthreads();
    if (kh == 1) {
#pragma unroll
        for (int j = 0; j < 8; j++) {
            const int c0 = j * 8 + (l & 3) * 2;
            Cs[lr][c0]         += acc[j][0];
            Cs[lr][c0 + 1]     += acc[j][1];
            Cs[lr + 8][c0]     += acc[j][2];
            Cs[lr + 8][c0 + 1] += acc[j][3];
        }
        if ((l & 3) == 0) { Zs[lr] += acc[8][0]; Zs[lr + 8] += acc[8][2]; }
    }
    __syncthreads();
    if (tid < 64) Zr[tid] = 1.0f / Zs[tid];
    __syncthreads();

    {
        const int d = tid >> 2, seg = tid & 3;
        float* go = out + ((size_t)(bb * DDIM + d)) * HW + row0 + seg * 16;
#pragma unroll
        for (int i = 0; i < 4; i++) {
            const int n = seg * 16 + i * 4;
            float4 o;
            o.x = Cs[n + 0][d] * Zr[n + 0];
            o.y = Cs[n + 1][d] * Zr[n + 1];
            o.z = Cs[n + 2][d] * Zr[n + 2];
            o.w = Cs[n + 3][d] * Zr[n + 3];
            *(float4*)(go + i * 4) = o;
        }
    }
}

// ---------------------------------------------------------------------------
extern "C" void kernel_launch(void* const* d_in, const int* in_sizes, int n_in,
                              void* d_out, int out_size) {
    const float* sim  = (const float*)d_in[0];  // [4, 4096, 4096] fp32
    const float* w    = (const float*)d_in[1];  // [64, 2] fp32
    const float* bias = (const float*)d_in[2];  // [64] fp32
    float* out = (float*)d_out;                 // [4, 64, 64, 64] fp32

    pos_enc_kernel<<<(NSLICE * 512 + 255) / 256, 256>>>(w, bias);

    dim3 grid(HW / 64, 4);
    gp_kernel<<<grid, 256>>>(sim, out);
}